// round 11
// baseline (speedup 1.0000x reference)
#include <cuda_runtime.h>
#include <cstdint>

// L1LossWithPenalty — dual-path streaming: TMA (pred) + consumer LDGSTS (tgt).
// out = (1/N) * sum_i [ sum_c |pred[i,c]-tgt[i,c]| ] * penalty[argmax pred_i, argmax tgt_i]
// N = 1048576, C = 27.  226 MB streamed -> HBM-bound.
//
// R10 vs R7/R8/R9 (plateau 5.2-5.7 TB/s, dram_active only ~65-70% => request
// generation leaves DRAM idle 30% of cycles):
//  - producer warp TMAs ONLY pred (1 bulk copy/stage, expect_tx=13824B);
//  - consumer warps (idle ~85%) issue tgt via cp.async.cg into the other half
//    of each stage, depth-3 wait_group pipeline;
//  => two independent per-SM request engines feed the LTS concurrently.
//  - consumer-scoped named barriers (bar.sync 1,128) give WAR + visibility for
//    the LDGSTS half; mbarrier full/empty ring still protects the TMA half.

#define C        27
#define ROWS     128                  // rows per tile (= consumer threads)
#define CONS     128                  // consumer threads (4 warps)
#define THREADS  160                  // + 1 producer warp
#define TILE_F   (ROWS * C)           // 3456 floats per array
#define TILE_B   (TILE_F * 4)         // 13824 bytes per array
#define TILE_4   (TILE_F / 4)         // 864 float4
#define FULLIT   (TILE_4 / CONS)      // 6
#define REM      (TILE_4 - FULLIT * CONS) // 96
#define STAGE_F  (2 * TILE_F)         // pred half + tgt half
#define STAGES   4
#define SMEM_BYTES (STAGES * STAGE_F * 4)   // 110592 B dynamic
#define GRID     296

__device__ double   g_acc;
__device__ unsigned g_count;

// ---- mbarrier / TMA / cp.async primitives ----
#define MBARRIER_INIT(addr, cnt) \
    asm volatile("mbarrier.init.shared.b64 [%0], %1;" :: "r"(addr), "r"(cnt) : "memory")

#define MBARRIER_ARRIVE(addr) \
    asm volatile("mbarrier.arrive.release.cta.shared.b64 _, [%0];" :: "r"(addr) : "memory")

#define MBARRIER_EXPECT_TX(addr, bytes) \
    asm volatile("mbarrier.arrive.expect_tx.shared.b64 _, [%0], %1;" \
                 :: "r"(addr), "r"(bytes) : "memory")

#define MBARRIER_WAIT_PARITY(addr, parity) do {                                   \
    uint32_t _mbar = (addr); uint32_t _par = (parity); uint32_t _done;            \
    asm volatile("{\n\t.reg .pred p;\n\t"                                         \
        "mbarrier.try_wait.parity.acquire.cta.shared::cta.b64 p, [%1], %2;\n\t"   \
        "selp.b32 %0, 1, 0, p;\n\t}"                                              \
        : "=r"(_done) : "r"(_mbar), "r"(_par) : "memory");                        \
    if (!_done) {                                                                 \
        asm volatile("{\n\t.reg .pred P1;\n\t"                                    \
            "WL_%=:\n\t"                                                          \
            "mbarrier.try_wait.parity.acquire.cta.shared::cta.b64 P1, [%0], %1, 0x989680;\n\t" \
            "@P1 bra.uni WD_%=;\n\t"                                              \
            "bra.uni WL_%=;\n\t"                                                  \
            "WD_%=:\n\t}" :: "r"(_mbar), "r"(_par) : "memory");                   \
    }                                                                             \
} while (0)

#define MBARRIER_WAIT_PARITY_RELAXED(addr, parity) do {                           \
    uint32_t _mbar = (addr); uint32_t _par = (parity); uint32_t _done;            \
    asm volatile("{\n\t.reg .pred p;\n\t"                                         \
        "mbarrier.try_wait.parity.relaxed.cta.shared::cta.b64 p, [%1], %2, 0x989680;\n\t" \
        "selp.b32 %0, 1, 0, p;\n\t}"                                              \
        : "=r"(_done) : "r"(_mbar), "r"(_par) : "memory");                        \
    if (!_done) {                                                                 \
        asm volatile("{\n\t.reg .pred P1;\n\t"                                    \
            "WL_%=:\n\t"                                                          \
            "mbarrier.try_wait.parity.relaxed.cta.shared::cta.b64 P1, [%0], %1, 0x989680;\n\t" \
            "@P1 bra.uni WD_%=;\n\t"                                              \
            "bra.uni WL_%=;\n\t"                                                  \
            "WD_%=:\n\t}" :: "r"(_mbar), "r"(_par) : "memory");                   \
    }                                                                             \
} while (0)

__device__ __forceinline__ void tma_bulk_g2s(uint32_t smem_dst, const void* gmem_src,
                                             uint32_t bytes, uint32_t mbar) {
    asm volatile(
        "cp.async.bulk.shared::cluster.global.mbarrier::complete_tx::bytes "
        "[%0], [%1], %2, [%3];"
        :: "r"(smem_dst), "l"(gmem_src), "r"(bytes), "r"(mbar) : "memory");
}

__device__ __forceinline__ void cp16(float* smem_dst, const float4* gmem_src) {
    unsigned saddr = (unsigned)__cvta_generic_to_shared(smem_dst);
    asm volatile("cp.async.cg.shared.global [%0], [%1], 16;\n"
                 :: "r"(saddr), "l"(gmem_src) : "memory");
}
__device__ __forceinline__ void cp_commit() {
    asm volatile("cp.async.commit_group;\n" ::: "memory");
}
__device__ __forceinline__ void cp_wait3() {
    asm volatile("cp.async.wait_group 3;\n" ::: "memory");
}
#define CONS_BAR() asm volatile("bar.sync 1, 128;" ::: "memory")

__global__ __launch_bounds__(THREADS)
void l1pen_kernel(const float* __restrict__ pred,
                  const float* __restrict__ tgt,
                  const float* __restrict__ pen,
                  int nrows,
                  float* __restrict__ out)
{
    extern __shared__ float dynsm[];            // [STAGES][pred TILE_F | tgt TILE_F]
    __shared__ alignas(16) unsigned long long mbars[2 * STAGES];
    __shared__ float s_warp[CONS / 32];

    const int tid    = threadIdx.x;
    const int wid    = tid >> 5;
    const int nfull  = nrows / ROWS;            // 8192 full tiles for N=1M
    const int ntiles = (nrows + ROWS - 1) / ROWS;
    const int stride = gridDim.x;

    const uint32_t mb0 = (uint32_t)__cvta_generic_to_shared(mbars);
    auto full_addr  = [&](int s) { return mb0 + (uint32_t)(2 * s) * 8u; };
    auto empty_addr = [&](int s) { return mb0 + (uint32_t)(2 * s + 1) * 8u; };

    if (tid == 0) {
        #pragma unroll
        for (int s = 0; s < STAGES; s++) {
            MBARRIER_INIT(full_addr(s), 1u);                 // producer expect_tx
            MBARRIER_INIT(empty_addr(s), (uint32_t)(CONS / 32)); // 1 arrive/consumer warp
        }
    }
    __syncthreads();

    float acc = 0.0f;

    if (wid == CONS / 32) {
        // -------- producer warp: TMA streams pred only --------
        if ((tid & 31) == 0) {
            int s = 0, phase = 1;
            for (int tile = blockIdx.x; tile < nfull; tile += stride) {
                MBARRIER_WAIT_PARITY_RELAXED(empty_addr(s), phase);
                MBARRIER_EXPECT_TX(full_addr(s), (uint32_t)TILE_B);
                const uint32_t dst =
                    (uint32_t)__cvta_generic_to_shared(dynsm + s * STAGE_F);
                tma_bulk_g2s(dst, pred + (long)tile * TILE_F, TILE_B, full_addr(s));
                if (++s == STAGES) { s = 0; phase ^= 1; }
            }
        }
    } else {
        // -------- consumer warps: LDGSTS tgt + compute --------
        // tgt half of stage s lives at dynsm + s*STAGE_F + TILE_F.
        auto issue_tgt = [&](int tile, int s) {
            float* st = dynsm + s * STAGE_F + TILE_F;
            const float4* t4 = (const float4*)(tgt + (long)tile * TILE_F);
            #pragma unroll
            for (int k = 0; k < FULLIT; k++)
                cp16(st + (tid + k * CONS) * 4, t4 + tid + k * CONS);
            if (tid < REM)
                cp16(st + (FULLIT * CONS + tid) * 4, t4 + FULLIT * CONS + tid);
        };

        // Prologue: fill tgt pipeline 3 deep (one commit group each).
        #pragma unroll
        for (int p = 0; p < STAGES - 1; p++) {
            int t = blockIdx.x + p * stride;
            if (t < nfull)
                issue_tgt(t, p);
            cp_commit();
        }

        int s = 0, phase = 0, it = 0;
        for (int tile = blockIdx.x; tile < ntiles; tile += stride, it++) {
            if (tile < nfull) {
                // WAR: everyone done reading stage (it+3)%4 (read at it-1).
                CONS_BAR();
                const int ahead = tile + (STAGES - 1) * stride;
                if (ahead < nfull)
                    issue_tgt(ahead, (it + STAGES - 1) % STAGES);
                cp_commit();                    // uniform 1 group/iter
                cp_wait3();                     // own group for stage s done
                CONS_BAR();                     // cross-thread visibility of tgt s
                MBARRIER_WAIT_PARITY(full_addr(s), phase);   // pred s (TMA) ready

                const float* __restrict__ pr = dynsm + s * STAGE_F + tid * C;
                const float* __restrict__ tr = pr + TILE_F;
                float l1 = 0.0f;
                float pmax = pr[0], tmax = tr[0];
                int   pidx = 0,     tidx = 0;
                #pragma unroll
                for (int c = 0; c < C; c++) {
                    float a = pr[c];
                    float b = tr[c];
                    l1 += fabsf(a - b);
                    if (a > pmax) { pmax = a; pidx = c; }   // strict > == jnp.argmax ties
                    if (b > tmax) { tmax = b; tidx = c; }
                }
                acc += l1 * __ldg(&pen[pidx * C + tidx]);
                __syncwarp();
                if ((tid & 31) == 0)
                    MBARRIER_ARRIVE(empty_addr(s));          // pred half reusable
                if (++s == STAGES) { s = 0; phase ^= 1; }
            } else {
                // ragged last tile (dead for N=1M): direct global reads
                const int rows = nrows - nfull * ROWS;
                if (tid < rows) {
                    const long base = (long)(nfull * ROWS + tid) * C;
                    float l1 = 0.0f;
                    float pmax = pred[base], tmax = tgt[base];
                    int   pidx = 0,          tidx = 0;
                    #pragma unroll
                    for (int c = 0; c < C; c++) {
                        float a = pred[base + c];
                        float b = tgt [base + c];
                        l1 += fabsf(a - b);
                        if (a > pmax) { pmax = a; pidx = c; }
                        if (b > tmax) { tmax = b; tidx = c; }
                    }
                    acc += l1 * __ldg(&pen[pidx * C + tidx]);
                }
            }
        }

        // warp reduce (consumer warps only)
        #pragma unroll
        for (int off = 16; off > 0; off >>= 1)
            acc += __shfl_down_sync(0xffffffffu, acc, off);
        if ((tid & 31) == 0)
            s_warp[wid] = acc;
    }

    __syncthreads();   // all 5 warps: consumers done writing s_warp

    if (tid == 0) {
        float s = 0.0f;
        #pragma unroll
        for (int w = 0; w < CONS / 32; w++)
            s += s_warp[w];

        atomicAdd(&g_acc, (double)s);
        __threadfence();
        unsigned done = atomicAdd(&g_count, 1u) + 1u;
        if (done == gridDim.x) {
            __threadfence();
            double v = atomicAdd(&g_acc, 0.0);
            *out = (float)(v / (double)nrows);
            g_acc = 0.0;              // self-reset for next graph replay
            __threadfence();
            g_count = 0u;
        }
    }
}

extern "C" void kernel_launch(void* const* d_in, const int* in_sizes, int n_in,
                              void* d_out, int out_size)
{
    int pen_i = -1;
    for (int i = 0; i < n_in; i++)
        if (in_sizes[i] == C * C) { pen_i = i; break; }
    int big[2], nb = 0;
    for (int i = 0; i < n_in && nb < 2; i++)
        if (i != pen_i) big[nb++] = i;

    const float* pred = (const float*)d_in[big[0]];
    const float* tgt  = (const float*)d_in[big[1]];
    const float* pen  = (const float*)d_in[pen_i];

    const int nrows = in_sizes[big[0]] / C;

    cudaFuncSetAttribute(l1pen_kernel,
                         cudaFuncAttributeMaxDynamicSharedMemorySize, SMEM_BYTES);

    l1pen_kernel<<<GRID, THREADS, SMEM_BYTES>>>(pred, tgt, pen, nrows,
                                                (float*)d_out);
}

// round 12
// speedup vs baseline: 1.0744x; 1.0744x over previous
#include <cuda_runtime.h>
#include <cstdint>

// L1LossWithPenalty — R7 revert (best measured: kernel 40.1us, DRAM 70.3%)
// + L2 evict_first cache hint on the TMA bulk copies (stream-once data).
// out = (1/N) * sum_i [ sum_c |pred[i,c]-tgt[i,c]| ] * penalty[argmax pred_i, argmax tgt_i]
// N = 1048576, C = 27.  226 MB streamed -> HBM-bound.
//
// Evidence across R5-R10: all request-generation schemes plateau at
// 5.0-5.75 TB/s; R7's warp-specialized TMA @ 2 blocks/SM is the max and every
// deviation from it regressed. This round restores R7 exactly and adds only
// an orthogonal L2 policy hint.

#define C        27
#define ROWS     128                  // rows per tile (= consumer threads)
#define CONS     128                  // consumer threads (4 warps)
#define THREADS  160                  // + 1 producer warp
#define TILE_F   (ROWS * C)           // 3456 floats
#define TILE_B   (TILE_F * 4)         // 13824 bytes per array per tile
#define STAGE_F  (2 * TILE_F)
#define STAGES   4
#define SMEM_BYTES (STAGES * STAGE_F * 4)   // 110592 B
#define GRID     296

__device__ double   g_acc;
__device__ unsigned g_count;

// ---- mbarrier / TMA-bulk primitives ----
#define MBARRIER_INIT(addr, cnt) \
    asm volatile("mbarrier.init.shared.b64 [%0], %1;" :: "r"(addr), "r"(cnt) : "memory")

#define MBARRIER_ARRIVE(addr) \
    asm volatile("mbarrier.arrive.shared.b64 _, [%0];" :: "r"(addr) : "memory")

#define MBARRIER_EXPECT_TX(addr, bytes) \
    asm volatile("mbarrier.arrive.expect_tx.shared.b64 _, [%0], %1;" \
                 :: "r"(addr), "r"(bytes) : "memory")

#define MBARRIER_WAIT_PARITY(addr, parity) do {                                   \
    uint32_t _mbar = (addr); uint32_t _par = (parity); uint32_t _done;            \
    asm volatile("{\n\t.reg .pred p;\n\t"                                         \
        "mbarrier.try_wait.parity.acquire.cta.shared::cta.b64 p, [%1], %2;\n\t"   \
        "selp.b32 %0, 1, 0, p;\n\t}"                                              \
        : "=r"(_done) : "r"(_mbar), "r"(_par) : "memory");                        \
    if (!_done) {                                                                 \
        asm volatile("{\n\t.reg .pred P1;\n\t"                                    \
            "WL_%=:\n\t"                                                          \
            "mbarrier.try_wait.parity.acquire.cta.shared::cta.b64 P1, [%0], %1, 0x989680;\n\t" \
            "@P1 bra.uni WD_%=;\n\t"                                              \
            "bra.uni WL_%=;\n\t"                                                  \
            "WD_%=:\n\t}" :: "r"(_mbar), "r"(_par) : "memory");                   \
    }                                                                             \
} while (0)

#define MBARRIER_WAIT_PARITY_RELAXED(addr, parity) do {                           \
    uint32_t _mbar = (addr); uint32_t _par = (parity); uint32_t _done;            \
    asm volatile("{\n\t.reg .pred p;\n\t"                                         \
        "mbarrier.try_wait.parity.relaxed.cta.shared::cta.b64 p, [%1], %2, 0x989680;\n\t" \
        "selp.b32 %0, 1, 0, p;\n\t}"                                              \
        : "=r"(_done) : "r"(_mbar), "r"(_par) : "memory");                        \
    if (!_done) {                                                                 \
        asm volatile("{\n\t.reg .pred P1;\n\t"                                    \
            "WL_%=:\n\t"                                                          \
            "mbarrier.try_wait.parity.relaxed.cta.shared::cta.b64 P1, [%0], %1, 0x989680;\n\t" \
            "@P1 bra.uni WD_%=;\n\t"                                              \
            "bra.uni WL_%=;\n\t"                                                  \
            "WD_%=:\n\t}" :: "r"(_mbar), "r"(_par) : "memory");                   \
    }                                                                             \
} while (0)

// Bulk copy with L2 evict_first policy (stream-once data: don't retain in L2).
__device__ __forceinline__ void tma_bulk_g2s_ef(uint32_t smem_dst, const void* gmem_src,
                                                uint32_t bytes, uint32_t mbar,
                                                uint64_t policy) {
    asm volatile(
        "cp.async.bulk.shared::cluster.global.mbarrier::complete_tx::bytes.L2::cache_hint "
        "[%0], [%1], %2, [%3], %4;"
        :: "r"(smem_dst), "l"(gmem_src), "r"(bytes), "r"(mbar), "l"(policy)
        : "memory");
}

__global__ __launch_bounds__(THREADS)
void l1pen_kernel(const float* __restrict__ pred,
                  const float* __restrict__ tgt,
                  const float* __restrict__ pen,
                  int nrows,
                  float* __restrict__ out)
{
    extern __shared__ float dynsm[];            // [STAGES][2][TILE_F]
    __shared__ alignas(16) unsigned long long mbars[2 * STAGES]; // full/empty pairs
    __shared__ float s_warp[CONS / 32];

    const int tid    = threadIdx.x;
    const int wid    = tid >> 5;
    const int nfull  = nrows / ROWS;            // full tiles (8192 for N=1M)
    const int ntiles = (nrows + ROWS - 1) / ROWS;
    const int stride = gridDim.x;

    const uint32_t mb0 = (uint32_t)__cvta_generic_to_shared(mbars);
    auto full_addr  = [&](int s) { return mb0 + (uint32_t)(2 * s) * 8u; };
    auto empty_addr = [&](int s) { return mb0 + (uint32_t)(2 * s + 1) * 8u; };

    if (tid == 0) {
        #pragma unroll
        for (int s = 0; s < STAGES; s++) {
            MBARRIER_INIT(full_addr(s), 1u);               // producer's expect_tx arrive
            MBARRIER_INIT(empty_addr(s), (uint32_t)CONS);  // all consumers arrive
        }
    }
    __syncthreads();

    float acc = 0.0f;

    if (wid == 4) {
        // -------- producer warp (lane 0 only) --------
        if ((tid & 31) == 0) {
            uint64_t policy;
            asm volatile("createpolicy.fractional.L2::evict_first.b64 %0, 1.0;"
                         : "=l"(policy));
            int s = 0, phase = 1;                // phase=1: first empty-wait passes
            for (int tile = blockIdx.x; tile < nfull; tile += stride) {
                MBARRIER_WAIT_PARITY_RELAXED(empty_addr(s), phase);
                MBARRIER_EXPECT_TX(full_addr(s), 2u * TILE_B);
                const uint32_t dst =
                    (uint32_t)__cvta_generic_to_shared(dynsm + s * STAGE_F);
                tma_bulk_g2s_ef(dst,          pred + (long)tile * TILE_F, TILE_B,
                                full_addr(s), policy);
                tma_bulk_g2s_ef(dst + TILE_B, tgt  + (long)tile * TILE_F, TILE_B,
                                full_addr(s), policy);
                if (++s == STAGES) { s = 0; phase ^= 1; }
            }
        }
    } else {
        // -------- consumer warps (128 threads, 1 row each per tile) --------
        int s = 0, phase = 0;
        for (int tile = blockIdx.x; tile < ntiles; tile += stride) {
            if (tile < nfull) {
                MBARRIER_WAIT_PARITY(full_addr(s), phase);   // acquire: TMA data visible
                const float* __restrict__ pr = dynsm + s * STAGE_F + tid * C;
                const float* __restrict__ tr = pr + TILE_F;
                float l1 = 0.0f;
                float pmax = pr[0], tmax = tr[0];
                int   pidx = 0,     tidx = 0;
                #pragma unroll
                for (int c = 0; c < C; c++) {
                    float a = pr[c];
                    float b = tr[c];
                    l1 += fabsf(a - b);
                    if (a > pmax) { pmax = a; pidx = c; }   // strict > == jnp.argmax ties
                    if (b > tmax) { tmax = b; tidx = c; }
                }
                acc += l1 * __ldg(&pen[pidx * C + tidx]);
                MBARRIER_ARRIVE(empty_addr(s));              // release: reads done
                if (++s == STAGES) { s = 0; phase ^= 1; }
            } else {
                // ragged last tile (dead for N=1M): direct global reads
                const int rows = nrows - nfull * ROWS;
                if (tid < rows) {
                    const long base = (long)(nfull * ROWS + tid) * C;
                    float l1 = 0.0f;
                    float pmax = pred[base], tmax = tgt[base];
                    int   pidx = 0,          tidx = 0;
                    #pragma unroll
                    for (int c = 0; c < C; c++) {
                        float a = pred[base + c];
                        float b = tgt [base + c];
                        l1 += fabsf(a - b);
                        if (a > pmax) { pmax = a; pidx = c; }
                        if (b > tmax) { tmax = b; tidx = c; }
                    }
                    acc += l1 * __ldg(&pen[pidx * C + tidx]);
                }
            }
        }

        // warp reduce (consumer warps only)
        #pragma unroll
        for (int off = 16; off > 0; off >>= 1)
            acc += __shfl_down_sync(0xffffffffu, acc, off);
        if ((tid & 31) == 0)
            s_warp[wid] = acc;
    }

    __syncthreads();   // all 5 warps: consumers done writing s_warp

    if (tid == 0) {
        float s = 0.0f;
        #pragma unroll
        for (int w = 0; w < CONS / 32; w++)
            s += s_warp[w];

        atomicAdd(&g_acc, (double)s);
        __threadfence();
        unsigned done = atomicAdd(&g_count, 1u) + 1u;
        if (done == gridDim.x) {
            __threadfence();
            double v = atomicAdd(&g_acc, 0.0);
            *out = (float)(v / (double)nrows);
            g_acc = 0.0;              // self-reset for next graph replay
            __threadfence();
            g_count = 0u;
        }
    }
}

extern "C" void kernel_launch(void* const* d_in, const int* in_sizes, int n_in,
                              void* d_out, int out_size)
{
    int pen_i = -1;
    for (int i = 0; i < n_in; i++)
        if (in_sizes[i] == C * C) { pen_i = i; break; }
    int big[2], nb = 0;
    for (int i = 0; i < n_in && nb < 2; i++)
        if (i != pen_i) big[nb++] = i;

    const float* pred = (const float*)d_in[big[0]];
    const float* tgt  = (const float*)d_in[big[1]];
    const float* pen  = (const float*)d_in[pen_i];

    const int nrows = in_sizes[big[0]] / C;

    cudaFuncSetAttribute(l1pen_kernel,
                         cudaFuncAttributeMaxDynamicSharedMemorySize, SMEM_BYTES);

    l1pen_kernel<<<GRID, THREADS, SMEM_BYTES>>>(pred, tgt, pen, nrows,
                                                (float*)d_out);
}